// round 13
// baseline (speedup 1.0000x reference)
#include <cuda_runtime.h>
#include <cuda_bf16.h>

#define NT 2000
#define NS 512
#define NH 64
#define NSNH (NS * NH)

// Output packing (concatenated flattened tuple, float32):
//   Q  : [NT, NS]        at 0
//   C  : [NT, NS]        at 1,024,000
//   S  : [NT, NS, NH]    at 2,048,000
//   H1 : [NT, NS, NH]    at 67,584,000
//   H2 : [NT, NS, NH]    at 133,120,000
//   Qs : [NT, NS, 3]     at 198,656,000
#define OFF_C   1024000
#define OFF_S   2048000
#define OFF_H1  67584000
#define OFF_H2  133120000
#define OFF_QS  198656000

__device__ __forceinline__ float sigmoidf(float x) {
    return 1.0f / (1.0f + expf(-x));
}

// 4 time segments per site; each segment = 16 chunks of 32 steps (seg3 ends
// ragged: chunks 48..62, last chunk 16 steps).
#define SEG_CHUNKS 16

__global__ void __launch_bounds__(32, 16)
soil_cq_kernel(const float* __restrict__ P, const float* __restrict__ T,
               const float* __restrict__ E,
               const float* __restrict__ w,  const float* __restrict__ wk1,
               const float* __restrict__ wk2, const float* __restrict__ we1,
               const float* __restrict__ we2, const float* __restrict__ wl,
               const float* __restrict__ wo,  const float* __restrict__ wc,
               float* __restrict__ out)
{
    const int lane = threadIdx.x;             // 0..31
    const int site = blockIdx.x >> 2;         // 0..511
    const int seg  = blockIdx.x & 3;          // time segment 0..3
    const int c_start = seg * SEG_CHUNKS;     // first FULL chunk
    const int c_end   = (seg == 3) ? 63 : (c_start + SEG_CHUNKS);
    const int j0 = lane * 2;
    const int j1 = j0 + 1;

    // per-lane partial sums, [step][lane], padded to 33: conflict-free
    // transposed reads in phase 2
    __shared__ float q1b[32][33];
    __shared__ float q2b[32][33];
    __shared__ float qcb[32][33];
    __shared__ float4 fbuf[2][32];            // forcing chunks (p,t,e,_)

    // ---- per-thread parameter precompute (2 hidden units per lane) ----
    const float ew0 = expf(w[j0]) + 1.0f,  ew1 = expf(w[j1]) + 1.0f;
    const float sk10 = sigmoidf(wk1[j0]),  sk11 = sigmoidf(wk1[j1]);
    const float sk20 = sigmoidf(wk2[j0]),  sk21 = sigmoidf(wk2[j1]);
    const float se10 = sigmoidf(we1[j0]),  se11 = sigmoidf(we1[j1]);
    const float se20 = sigmoidf(we2[j0]),  se21 = sigmoidf(we2[j1]);
    const float L0   = expf(wl[j0]),       L1   = expf(wl[j1]);
    const float csk10 = 1.0f - sk10,        csk11 = 1.0f - sk11;
    const float csk20 = 1.0f - 2.0f * sk20, csk21 = 1.0f - 2.0f * sk21;

    // softmax(wo) across the warp's 64 units
    float ex0 = expf(wo[j0]), ex1 = expf(wo[j1]);
    float esum = ex0 + ex1;
    #pragma unroll
    for (int o = 16; o; o >>= 1) esum += __shfl_xor_sync(0xffffffffu, esum, o);
    const float a0 = ex0 / esum, a1 = ex1 / esum;
    const float ar0 = a0 / (sk20 * (1.0f + expf(wc[j0])));
    const float ar1 = a1 / (sk21 * (1.0f + expf(wc[j1])));

    // ---- state in registers ----
    float s0 = 0.f, s1 = 0.f, h10 = 0.f, h11 = 0.f, h20 = 0.f, h21 = 0.f;

    // ---- state output pointers, positioned at this segment's first full step ----
    float* Sp  = out + OFF_S  + (size_t)site * NH + j0
                     + (size_t)c_start * 32 * NSNH;
    float* H1p = out + OFF_H1 + (size_t)site * NH + j0
                     + (size_t)c_start * 32 * NSNH;
    float* H2p = out + OFF_H2 + (size_t)site * NH + j0
                     + (size_t)c_start * 32 * NSNH;

    // ---- stage chunk-0 forcings ----
    fbuf[0][lane] = make_float4(P[lane * NS + site],
                                T[lane * NS + site],
                                E[lane * NS + site], 0.f);

    #pragma unroll 1
    for (int c = 0; c < c_end; ++c) {
        const int buf = c & 1;
        const int t0  = c * 32;
        const int rem = (NT - t0 < 32) ? (NT - t0) : 32;   // 16 only at c==62

        // prefetch next chunk's forcings into registers
        float pN = 0.f, tN = 0.f, eN = 0.f;
        {
            const int tn = t0 + 32 + lane;
            if (tn < NT) {
                pN = P[tn * NS + site];
                tN = T[tn * NS + site];
                eN = E[tn * NS + site];
            }
        }

        __syncwarp();   // fbuf[buf] staged; prev phase-2 done reading smem

        if (c < c_start) {
            // ========== warm-up: recurrence only (bitwise-identical math) ==========
            #pragma unroll 8
            for (int i = 0; i < 32; ++i) {
                const float4 f = fbuf[buf][i];
                const float p = f.x, t = f.y, e = f.z;

                const float trel = fmaxf(t, 0.0f);
                const float ppos = (t > 0.0f) ? p : 0.0f;
                const float pneg = (t < 0.0f) ? p : 0.0f;

                const float m0   = fminf(trel * ew0, s0);
                s0 = s0 - m0 + pneg;
                const float x0   = ppos + m0;
                const float h2x0 = h20 + x0;
                const float h1a0 = fmaxf(h10 + h2x0 - L0, 0.0f);
                const float h2a0 = fminf(h1a0 + h2x0, L0);
                h10 = fmaxf(fmaf(h1a0, csk10, -e * se10), 0.0f);
                h20 = fmaxf(fmaf(h2a0, csk20, -e * se20), 0.0f);

                const float m1   = fminf(trel * ew1, s1);
                s1 = s1 - m1 + pneg;
                const float x1   = ppos + m1;
                const float h2x1 = h21 + x1;
                const float h1a1 = fmaxf(h11 + h2x1 - L1, 0.0f);
                const float h2a1 = fminf(h1a1 + h2x1, L1);
                h11 = fmaxf(fmaf(h1a1, csk11, -e * se11), 0.0f);
                h21 = fmaxf(fmaf(h2a1, csk21, -e * se21), 0.0f);
            }
        } else {
            // ================= full: recurrence + outputs =================
            #pragma unroll 8
            for (int i = 0; i < rem; ++i) {
                const float4 f = fbuf[buf][i];
                const float p = f.x, t = f.y, e = f.z;

                const float trel = fmaxf(t, 0.0f);
                const float ppos = (t > 0.0f) ? p : 0.0f;
                const float pneg = (t < 0.0f) ? p : 0.0f;

                const float m0   = fminf(trel * ew0, s0);
                s0 = s0 - m0 + pneg;
                const float x0   = ppos + m0;
                const float h2x0 = h20 + x0;
                const float h1a0 = fmaxf(h10 + h2x0 - L0, 0.0f);
                const float h2a0 = fminf(h1a0 + h2x0, L0);
                const float q10  = h1a0 * sk10;
                const float q20  = h2a0 * sk20;
                h10 = fmaxf(fmaf(h1a0, csk10, -e * se10), 0.0f);
                h20 = fmaxf(fmaf(h2a0, csk20, -e * se20), 0.0f);

                const float m1   = fminf(trel * ew1, s1);
                s1 = s1 - m1 + pneg;
                const float x1   = ppos + m1;
                const float h2x1 = h21 + x1;
                const float h1a1 = fmaxf(h11 + h2x1 - L1, 0.0f);
                const float h2a1 = fminf(h1a1 + h2x1, L1);
                const float q11  = h1a1 * sk11;
                const float q21  = h2a1 * sk21;
                h11 = fmaxf(fmaf(h1a1, csk11, -e * se11), 0.0f);
                h21 = fmaxf(fmaf(h2a1, csk21, -e * se21), 0.0f);

                // coalesced state stores (256B/warp/array)
                *(float2*)Sp  = make_float2(s0,  s1);
                *(float2*)H1p = make_float2(h10, h11);
                *(float2*)H2p = make_float2(h20, h21);
                Sp  += NSNH;
                H1p += NSNH;
                H2p += NSNH;

                // stash per-lane partials (off critical path)
                q1b[i][lane] = q10 * a0  + q11 * a1;
                q2b[i][lane] = q20 * a0  + q21 * a1;
                qcb[i][lane] = q20 * ar0 + q21 * ar1;
            }
        }

        // stage next chunk's forcings
        fbuf[buf ^ 1][lane] = make_float4(pN, tN, eN, 0.f);

        __syncwarp();   // partials complete; fbuf[buf^1] staged

        // ===== phase 2 (full chunks only): lane i reduces step t0+i =====
        if (c >= c_start && lane < rem) {
            float a1a = 0.f, a1c = 0.f, a1e = 0.f, a1g = 0.f;
            float a2a = 0.f, a2c = 0.f, a2e = 0.f, a2g = 0.f;
            float aca = 0.f, acc = 0.f, ace = 0.f, acg = 0.f;
            const float* r1 = q1b[lane];
            const float* r2 = q2b[lane];
            const float* rc = qcb[lane];
            #pragma unroll
            for (int k = 0; k < 32; k += 4) {
                a1a += r1[k];     a2a += r2[k];     aca += rc[k];
                a1c += r1[k + 1]; a2c += r2[k + 1]; acc += rc[k + 1];
                a1e += r1[k + 2]; a2e += r2[k + 2]; ace += rc[k + 2];
                a1g += r1[k + 3]; a2g += r2[k + 3]; acg += rc[k + 3];
            }
            const float Qs1 = (a1a + a1c) + (a1e + a1g);
            const float Qs2 = (a2a + a2c) + (a2e + a2g);
            const float qcS = (aca + acc) + (ace + acg);
            const float Qk  = Qs1 + Qs2;
            const float cc  = __fdividef(qcS * (1.0f / 64.0f) + 1e-5f, Qk + 1e-5f);

            const int t = t0 + lane;
            out[t * NS + site]         = Qk;
            out[OFF_C + t * NS + site] = cc;
            float* qs = out + OFF_QS + ((size_t)t * NS + site) * 3;
            qs[0] = Qs1;
            qs[1] = Qs2;
            qs[2] = 0.0f;
        }
    }
}

extern "C" void kernel_launch(void* const* d_in, const int* in_sizes, int n_in,
                              void* d_out, int out_size)
{
    (void)in_sizes; (void)n_in; (void)out_size;
    soil_cq_kernel<<<NS * 4, 32>>>(
        (const float*)d_in[0], (const float*)d_in[1], (const float*)d_in[2],
        (const float*)d_in[3], (const float*)d_in[4], (const float*)d_in[5],
        (const float*)d_in[6], (const float*)d_in[7], (const float*)d_in[8],
        (const float*)d_in[9], (const float*)d_in[10],
        (float*)d_out);
}

// round 14
// speedup vs baseline: 1.4818x; 1.4818x over previous
#include <cuda_runtime.h>
#include <cuda_bf16.h>

#define NT 2000
#define NS 512
#define NH 64
#define NSNH (NS * NH)

// Output packing (concatenated flattened tuple, float32):
//   Q  : [NT, NS]        at 0
//   C  : [NT, NS]        at 1,024,000
//   S  : [NT, NS, NH]    at 2,048,000
//   H1 : [NT, NS, NH]    at 67,584,000
//   H2 : [NT, NS, NH]    at 133,120,000
//   Qs : [NT, NS, 3]     at 198,656,000
#define OFF_C   1024000
#define OFF_S   2048000
#define OFF_H1  67584000
#define OFF_H2  133120000
#define OFF_QS  198656000

// asymmetric 2-segment split: seg0 emits chunks [0,46), seg1 warms [0,46)
// then emits [46,63). Balanced for warm/full cost ratio ~0.65.
#define SPLIT_CHUNK 46

__device__ __forceinline__ float sigmoidf(float x) {
    return 1.0f / (1.0f + expf(-x));
}

__global__ void __launch_bounds__(32, 16)
soil_cq_kernel(const float* __restrict__ P, const float* __restrict__ T,
               const float* __restrict__ E,
               const float* __restrict__ w,  const float* __restrict__ wk1,
               const float* __restrict__ wk2, const float* __restrict__ we1,
               const float* __restrict__ we2, const float* __restrict__ wl,
               const float* __restrict__ wo,  const float* __restrict__ wc,
               float* __restrict__ out)
{
    const int lane = threadIdx.x;             // 0..31
    const int site = blockIdx.x >> 1;         // 0..511
    const int seg  = blockIdx.x & 1;          // time segment 0..1
    const int c_start = seg ? SPLIT_CHUNK : 0;
    const int c_end   = seg ? 63 : SPLIT_CHUNK;
    const int j0 = lane * 2;
    const int j1 = j0 + 1;

    // per-lane partial sums, [step][lane], padded to 33: conflict-free
    // transposed reads in phase 2
    __shared__ float q1b[32][33];
    __shared__ float q2b[32][33];
    __shared__ float qcb[32][33];
    __shared__ float4 fbuf[2][32];            // forcing chunks (p,t,e,_)

    // ---- per-thread parameter precompute (2 hidden units per lane) ----
    const float ew0 = expf(w[j0]) + 1.0f,  ew1 = expf(w[j1]) + 1.0f;
    const float sk10 = sigmoidf(wk1[j0]),  sk11 = sigmoidf(wk1[j1]);
    const float sk20 = sigmoidf(wk2[j0]),  sk21 = sigmoidf(wk2[j1]);
    const float se10 = sigmoidf(we1[j0]),  se11 = sigmoidf(we1[j1]);
    const float se20 = sigmoidf(we2[j0]),  se21 = sigmoidf(we2[j1]);
    const float L0   = expf(wl[j0]),       L1   = expf(wl[j1]);
    const float csk10 = 1.0f - sk10,        csk11 = 1.0f - sk11;
    const float csk20 = 1.0f - 2.0f * sk20, csk21 = 1.0f - 2.0f * sk21;

    // softmax(wo) across the warp's 64 units
    float ex0 = expf(wo[j0]), ex1 = expf(wo[j1]);
    float esum = ex0 + ex1;
    #pragma unroll
    for (int o = 16; o; o >>= 1) esum += __shfl_xor_sync(0xffffffffu, esum, o);
    const float a0 = ex0 / esum, a1 = ex1 / esum;
    const float ar0 = a0 / (sk20 * (1.0f + expf(wc[j0])));
    const float ar1 = a1 / (sk21 * (1.0f + expf(wc[j1])));

    // folded output coefficients: q1*a = h1a*(sk1*a), etc.
    const float ska10 = sk10 * a0,  ska11 = sk11 * a1;
    const float ska20 = sk20 * a0,  ska21 = sk21 * a1;
    const float skr20 = sk20 * ar0, skr21 = sk21 * ar1;

    // ---- state in registers ----
    float s0 = 0.f, s1 = 0.f, h10 = 0.f, h11 = 0.f, h20 = 0.f, h21 = 0.f;

    // ---- state output pointers, positioned at this segment's first full step ----
    float* Sp  = out + OFF_S  + (size_t)site * NH + j0
                     + (size_t)c_start * 32 * NSNH;
    float* H1p = out + OFF_H1 + (size_t)site * NH + j0
                     + (size_t)c_start * 32 * NSNH;
    float* H2p = out + OFF_H2 + (size_t)site * NH + j0
                     + (size_t)c_start * 32 * NSNH;

    // ---- stage chunk-0 forcings ----
    fbuf[0][lane] = make_float4(P[lane * NS + site],
                                T[lane * NS + site],
                                E[lane * NS + site], 0.f);

    #pragma unroll 1
    for (int c = 0; c < c_end; ++c) {
        const int buf = c & 1;
        const int t0  = c * 32;
        const int rem = (NT - t0 < 32) ? (NT - t0) : 32;   // 16 only at c==62

        // prefetch next chunk's forcings into registers
        float pN = 0.f, tN = 0.f, eN = 0.f;
        {
            const int tn = t0 + 32 + lane;
            if (tn < NT) {
                pN = P[tn * NS + site];
                tN = T[tn * NS + site];
                eN = E[tn * NS + site];
            }
        }

        __syncwarp();   // fbuf[buf] staged; prev phase-2 done reading smem

        if (c < c_start) {
            // ===== warm-up: recurrence only (bitwise-identical math, no stores) =====
            #pragma unroll 8
            for (int i = 0; i < 32; ++i) {
                const float4 f = fbuf[buf][i];
                const float p = f.x, t = f.y, e = f.z;

                const float trel = fmaxf(t, 0.0f);
                const float ppos = (t > 0.0f) ? p : 0.0f;
                const float pneg = (t < 0.0f) ? p : 0.0f;

                const float m0   = fminf(trel * ew0, s0);
                s0 = s0 - m0 + pneg;
                const float x0   = ppos + m0;
                const float h2x0 = h20 + x0;
                const float h1a0 = fmaxf(h10 + h2x0 - L0, 0.0f);
                const float h2a0 = fminf(h1a0 + h2x0, L0);
                h10 = fmaxf(fmaf(h1a0, csk10, -e * se10), 0.0f);
                h20 = fmaxf(fmaf(h2a0, csk20, -e * se20), 0.0f);

                const float m1   = fminf(trel * ew1, s1);
                s1 = s1 - m1 + pneg;
                const float x1   = ppos + m1;
                const float h2x1 = h21 + x1;
                const float h1a1 = fmaxf(h11 + h2x1 - L1, 0.0f);
                const float h2a1 = fminf(h1a1 + h2x1, L1);
                h11 = fmaxf(fmaf(h1a1, csk11, -e * se11), 0.0f);
                h21 = fmaxf(fmaf(h2a1, csk21, -e * se21), 0.0f);
            }
        } else {
            // ================= full: recurrence + outputs =================
            #pragma unroll 8
            for (int i = 0; i < rem; ++i) {
                const float4 f = fbuf[buf][i];
                const float p = f.x, t = f.y, e = f.z;

                const float trel = fmaxf(t, 0.0f);
                const float ppos = (t > 0.0f) ? p : 0.0f;
                const float pneg = (t < 0.0f) ? p : 0.0f;

                const float m0   = fminf(trel * ew0, s0);
                s0 = s0 - m0 + pneg;
                const float x0   = ppos + m0;
                const float h2x0 = h20 + x0;
                const float h1a0 = fmaxf(h10 + h2x0 - L0, 0.0f);
                const float h2a0 = fminf(h1a0 + h2x0, L0);
                h10 = fmaxf(fmaf(h1a0, csk10, -e * se10), 0.0f);
                h20 = fmaxf(fmaf(h2a0, csk20, -e * se20), 0.0f);

                const float m1   = fminf(trel * ew1, s1);
                s1 = s1 - m1 + pneg;
                const float x1   = ppos + m1;
                const float h2x1 = h21 + x1;
                const float h1a1 = fmaxf(h11 + h2x1 - L1, 0.0f);
                const float h2a1 = fminf(h1a1 + h2x1, L1);
                h11 = fmaxf(fmaf(h1a1, csk11, -e * se11), 0.0f);
                h21 = fmaxf(fmaf(h2a1, csk21, -e * se21), 0.0f);

                // coalesced state stores (256B/warp/array)
                *(float2*)Sp  = make_float2(s0,  s1);
                *(float2*)H1p = make_float2(h10, h11);
                *(float2*)H2p = make_float2(h20, h21);
                Sp  += NSNH;
                H1p += NSNH;
                H2p += NSNH;

                // stash per-lane partials (folded coefficients, off critical path)
                q1b[i][lane] = fmaf(h1a1, ska11, h1a0 * ska10);
                q2b[i][lane] = fmaf(h2a1, ska21, h2a0 * ska20);
                qcb[i][lane] = fmaf(h2a1, skr21, h2a0 * skr20);
            }
        }

        // stage next chunk's forcings
        fbuf[buf ^ 1][lane] = make_float4(pN, tN, eN, 0.f);

        __syncwarp();   // partials complete; fbuf[buf^1] staged

        // ===== phase 2 (full chunks only): lane i reduces step t0+i =====
        if (c >= c_start && lane < rem) {
            float a1a = 0.f, a1c = 0.f, a1e = 0.f, a1g = 0.f;
            float a2a = 0.f, a2c = 0.f, a2e = 0.f, a2g = 0.f;
            float aca = 0.f, acc = 0.f, ace = 0.f, acg = 0.f;
            const float* r1 = q1b[lane];
            const float* r2 = q2b[lane];
            const float* rc = qcb[lane];
            #pragma unroll
            for (int k = 0; k < 32; k += 4) {
                a1a += r1[k];     a2a += r2[k];     aca += rc[k];
                a1c += r1[k + 1]; a2c += r2[k + 1]; acc += rc[k + 1];
                a1e += r1[k + 2]; a2e += r2[k + 2]; ace += rc[k + 2];
                a1g += r1[k + 3]; a2g += r2[k + 3]; acg += rc[k + 3];
            }
            const float Qs1 = (a1a + a1c) + (a1e + a1g);
            const float Qs2 = (a2a + a2c) + (a2e + a2g);
            const float qcS = (aca + acc) + (ace + acg);
            const float Qk  = Qs1 + Qs2;
            const float cc  = __fdividef(qcS * (1.0f / 64.0f) + 1e-5f, Qk + 1e-5f);

            const int t = t0 + lane;
            out[t * NS + site]         = Qk;
            out[OFF_C + t * NS + site] = cc;
            float* qs = out + OFF_QS + ((size_t)t * NS + site) * 3;
            qs[0] = Qs1;
            qs[1] = Qs2;
            qs[2] = 0.0f;
        }
    }
}

extern "C" void kernel_launch(void* const* d_in, const int* in_sizes, int n_in,
                              void* d_out, int out_size)
{
    (void)in_sizes; (void)n_in; (void)out_size;
    soil_cq_kernel<<<NS * 2, 32>>>(
        (const float*)d_in[0], (const float*)d_in[1], (const float*)d_in[2],
        (const float*)d_in[3], (const float*)d_in[4], (const float*)d_in[5],
        (const float*)d_in[6], (const float*)d_in[7], (const float*)d_in[8],
        (const float*)d_in[9], (const float*)d_in[10],
        (float*)d_out);
}

// round 15
// speedup vs baseline: 1.6781x; 1.1325x over previous
#include <cuda_runtime.h>
#include <cuda_bf16.h>

#define NT 2000
#define NS 512
#define NH 64
#define NSNH (NS * NH)

// Output packing (concatenated flattened tuple, float32):
//   Q  : [NT, NS]        at 0
//   C  : [NT, NS]        at 1,024,000
//   S  : [NT, NS, NH]    at 2,048,000
//   H1 : [NT, NS, NH]    at 67,584,000
//   H2 : [NT, NS, NH]    at 133,120,000
//   Qs : [NT, NS, 3]     at 198,656,000
#define OFF_C   1024000
#define OFF_S   2048000
#define OFF_H1  67584000
#define OFF_H2  133120000
#define OFF_QS  198656000

__device__ __forceinline__ float sigmoidf(float x) {
    return 1.0f / (1.0f + expf(-x));
}

__global__ void __launch_bounds__(32, 16)
soil_cq_kernel(const float* __restrict__ P, const float* __restrict__ T,
               const float* __restrict__ E,
               const float* __restrict__ w,  const float* __restrict__ wk1,
               const float* __restrict__ wk2, const float* __restrict__ we1,
               const float* __restrict__ we2, const float* __restrict__ wl,
               const float* __restrict__ wo,  const float* __restrict__ wc,
               float* __restrict__ out)
{
    const int lane = threadIdx.x;           // 0..31
    const int site = blockIdx.x;            // 0..511
    const int j0 = lane * 2;
    const int j1 = j0 + 1;

    // [step][lane] packed partials (q1a, q2a, qc, 0); padded to 33 for
    // conflict-free transposed LDS.128 in phase 2
    __shared__ float4 pbuf[32][33];
    __shared__ float4 fbuf[2][32];          // forcing chunks (p,t,e,_)

    // ---- per-thread parameter precompute (2 hidden units per lane) ----
    const float ew0 = expf(w[j0]) + 1.0f,  ew1 = expf(w[j1]) + 1.0f;
    const float sk10 = sigmoidf(wk1[j0]),  sk11 = sigmoidf(wk1[j1]);
    const float sk20 = sigmoidf(wk2[j0]),  sk21 = sigmoidf(wk2[j1]);
    const float se10 = sigmoidf(we1[j0]),  se11 = sigmoidf(we1[j1]);
    const float se20 = sigmoidf(we2[j0]),  se21 = sigmoidf(we2[j1]);
    const float L0   = expf(wl[j0]),       L1   = expf(wl[j1]);
    const float csk10 = 1.0f - sk10,        csk11 = 1.0f - sk11;
    const float csk20 = 1.0f - 2.0f * sk20, csk21 = 1.0f - 2.0f * sk21;

    // softmax(wo) across the warp's 64 units
    float ex0 = expf(wo[j0]), ex1 = expf(wo[j1]);
    float esum = ex0 + ex1;
    #pragma unroll
    for (int o = 16; o; o >>= 1) esum += __shfl_xor_sync(0xffffffffu, esum, o);
    const float a0 = ex0 / esum, a1 = ex1 / esum;
    const float ar0 = a0 / (sk20 * (1.0f + expf(wc[j0])));
    const float ar1 = a1 / (sk21 * (1.0f + expf(wc[j1])));

    // folded output coefficients: q1*a = h1a*(sk1*a), etc.
    const float ska10 = sk10 * a0,  ska11 = sk11 * a1;
    const float ska20 = sk20 * a0,  ska21 = sk21 * a1;
    const float skr20 = sk20 * ar0, skr21 = sk21 * ar1;

    // ---- state in registers ----
    float s0 = 0.f, s1 = 0.f, h10 = 0.f, h11 = 0.f, h20 = 0.f, h21 = 0.f;

    // ---- state output pointers (coalesced float2 per warp) ----
    float* Sp  = out + OFF_S  + (size_t)site * NH + j0;
    float* H1p = out + OFF_H1 + (size_t)site * NH + j0;
    float* H2p = out + OFF_H2 + (size_t)site * NH + j0;

    // ---- stage chunk-0 forcings ----
    fbuf[0][lane] = make_float4(P[lane * NS + site],
                                T[lane * NS + site],
                                E[lane * NS + site], 0.f);

    #pragma unroll 1
    for (int c = 0; c < 63; ++c) {
        const int buf = c & 1;
        const int t0  = c * 32;
        const int rem = (c == 62) ? 16 : 32;

        // prefetch next chunk's forcings into registers (hidden under phase 1)
        float pN = 0.f, tN = 0.f, eN = 0.f;
        {
            const int tn = t0 + 32 + lane;
            if (tn < NT) {
                pN = P[tn * NS + site];
                tN = T[tn * NS + site];
                eN = E[tn * NS + site];
            }
        }

        __syncwarp();   // fbuf[buf] staged; prev phase-2 done reading pbuf

        // ================= phase 1: recurrence, no shuffles =================
        #pragma unroll 8
        for (int i = 0; i < rem; ++i) {
            const float4 f = fbuf[buf][i];
            const float p = f.x, t = f.y, e = f.z;

            const float trel = fmaxf(t, 0.0f);
            const float ppos = (t > 0.0f) ? p : 0.0f;
            const float pneg = (t < 0.0f) ? p : 0.0f;

            // ---- unit 0 ----
            const float m0   = fminf(trel * ew0, s0);
            s0 = s0 - m0 + pneg;
            const float x0   = ppos + m0;
            const float h2x0 = h20 + x0;
            const float h1a0 = fmaxf(h10 + h2x0 - L0, 0.0f);
            const float h2a0 = fminf(h1a0 + h2x0, L0);
            h10 = fmaxf(fmaf(h1a0, csk10, -e * se10), 0.0f);
            h20 = fmaxf(fmaf(h2a0, csk20, -e * se20), 0.0f);

            // ---- unit 1 ----
            const float m1   = fminf(trel * ew1, s1);
            s1 = s1 - m1 + pneg;
            const float x1   = ppos + m1;
            const float h2x1 = h21 + x1;
            const float h1a1 = fmaxf(h11 + h2x1 - L1, 0.0f);
            const float h2a1 = fminf(h1a1 + h2x1, L1);
            h11 = fmaxf(fmaf(h1a1, csk11, -e * se11), 0.0f);
            h21 = fmaxf(fmaf(h2a1, csk21, -e * se21), 0.0f);

            // ---- coalesced state stores (256B/warp/array) ----
            *(float2*)Sp  = make_float2(s0,  s1);
            *(float2*)H1p = make_float2(h10, h11);
            *(float2*)H2p = make_float2(h20, h21);
            Sp  += NSNH;
            H1p += NSNH;
            H2p += NSNH;

            // ---- packed per-lane partials: ONE STS.128 ----
            pbuf[i][lane] = make_float4(fmaf(h1a1, ska11, h1a0 * ska10),
                                        fmaf(h2a1, ska21, h2a0 * ska20),
                                        fmaf(h2a1, skr21, h2a0 * skr20),
                                        0.0f);
        }

        // stage next chunk's forcings
        fbuf[buf ^ 1][lane] = make_float4(pN, tN, eN, 0.f);

        __syncwarp();   // pbuf complete; fbuf[buf^1] staged

        // ====== phase 2: lane i reduces + emits outputs of step t0+i ======
        if (lane < rem) {
            const float4* row = pbuf[lane];
            float x0 = 0.f, x1 = 0.f, x2 = 0.f, x3 = 0.f;
            float y0 = 0.f, y1 = 0.f, y2 = 0.f, y3 = 0.f;
            float z0 = 0.f, z1 = 0.f, z2 = 0.f, z3 = 0.f;
            #pragma unroll
            for (int k = 0; k < 32; k += 4) {
                const float4 v0 = row[k],     v1 = row[k + 1];
                const float4 v2 = row[k + 2], v3 = row[k + 3];
                x0 += v0.x; x1 += v1.x; x2 += v2.x; x3 += v3.x;
                y0 += v0.y; y1 += v1.y; y2 += v2.y; y3 += v3.y;
                z0 += v0.z; z1 += v1.z; z2 += v2.z; z3 += v3.z;
            }
            const float Qs1 = (x0 + x1) + (x2 + x3);
            const float Qs2 = (y0 + y1) + (y2 + y3);
            const float qcS = (z0 + z1) + (z2 + z3);
            const float Qk  = Qs1 + Qs2;
            const float cc  = __fdividef(qcS * (1.0f / 64.0f) + 1e-5f, Qk + 1e-5f);

            const int t = t0 + lane;
            out[t * NS + site]         = Qk;
            out[OFF_C + t * NS + site] = cc;
            float* qs = out + OFF_QS + ((size_t)t * NS + site) * 3;
            qs[0] = Qs1;
            qs[1] = Qs2;
            qs[2] = 0.0f;
        }
    }
}

extern "C" void kernel_launch(void* const* d_in, const int* in_sizes, int n_in,
                              void* d_out, int out_size)
{
    (void)in_sizes; (void)n_in; (void)out_size;
    soil_cq_kernel<<<NS, 32>>>(
        (const float*)d_in[0], (const float*)d_in[1], (const float*)d_in[2],
        (const float*)d_in[3], (const float*)d_in[4], (const float*)d_in[5],
        (const float*)d_in[6], (const float*)d_in[7], (const float*)d_in[8],
        (const float*)d_in[9], (const float*)d_in[10],
        (float*)d_out);
}